// round 2
// baseline (speedup 1.0000x reference)
#include <cuda_runtime.h>
#include <math.h>

#define L_SEQ 2048
#define BATCH 2
#define EMB   1024
#define NH    16
#define DQKh  128     // per-head qk dim
#define QKD   2048    // total qk dim
#define DVh   64      // per-head v dim
#define NROWS 4096    // L*B

// ---------------- scratch (static device globals; no allocation) ------------
__device__ float g_qlin[(size_t)NROWS * QKD];   // 32MB  relu(q proj)*scale
__device__ float g_klin[(size_t)NROWS * QKD];   // 32MB  relu(k proj)
__device__ float g_vlin[(size_t)NROWS * EMB];   // 16MB  v proj
__device__ float g_attn[(size_t)NROWS * EMB];   // 16MB  attention output (l,b,e)
__device__ int   g_ws[NH * L_SEQ];              // per (head,row) window start

// ---------------- mask window-start table -----------------------------------
// Faithful port of _one_mask: head h keeps dims [ws, ws+32) of 128,
// ws = mm*h with rn = 96/h+1, i=l/rn, m=l%rn, mm = (i&1)? rn-1-m : m.
__global__ void build_ws_kernel() {
    int idx = blockIdx.x * blockDim.x + threadIdx.x;
    if (idx >= NH * L_SEQ) return;
    int h = idx / L_SEQ, l = idx % L_SEQ;
    int ws = 0;
    if (h > 0) {
        int rn = 96 / h + 1;
        int i = l / rn, m = l % rn;
        int mm = (i & 1) ? (rn - 1 - m) : m;
        ws = mm * h;
    }
    g_ws[idx] = ws;
}

// ---------------- SGEMM: C[M,N] = epilogue(A[M,K] @ W[N,K]^T + bias) --------
// MODE 0: +bias    MODE 1: relu(+bias)*scale    MODE 2: relu(+bias)
// BM=BN=128, BK=8, 256 threads, 8x8 per thread.
template <int MODE>
__global__ void __launch_bounds__(256) sgemm_bias(
    const float* __restrict__ A, const float* __restrict__ W,
    const float* __restrict__ bias, float* __restrict__ C,
    int M, int N, int K, float scale)
{
    __shared__ float As[8][128];
    __shared__ float Bs[8][128];
    int tid = threadIdx.x;
    int tx = tid & 15, ty = tid >> 4;
    int m0 = blockIdx.y * 128, n0 = blockIdx.x * 128;
    int lrow = tid >> 1;
    int lcol = (tid & 1) * 4;
    const float* Ap = A + (size_t)(m0 + lrow) * K + lcol;
    const float* Wp = W + (size_t)(n0 + lrow) * K + lcol;

    float acc[8][8] = {};
    for (int kt = 0; kt < K; kt += 8) {
        float4 av = *(const float4*)(Ap + kt);
        float4 bv = *(const float4*)(Wp + kt);
        As[lcol + 0][lrow] = av.x; As[lcol + 1][lrow] = av.y;
        As[lcol + 2][lrow] = av.z; As[lcol + 3][lrow] = av.w;
        Bs[lcol + 0][lrow] = bv.x; Bs[lcol + 1][lrow] = bv.y;
        Bs[lcol + 2][lrow] = bv.z; Bs[lcol + 3][lrow] = bv.w;
        __syncthreads();
        #pragma unroll
        for (int kk = 0; kk < 8; kk++) {
            float a[8], bb[8];
            #pragma unroll
            for (int i = 0; i < 8; i++) a[i]  = As[kk][ty * 8 + i];
            #pragma unroll
            for (int j = 0; j < 8; j++) bb[j] = Bs[kk][tx * 8 + j];
            #pragma unroll
            for (int i = 0; i < 8; i++)
                #pragma unroll
                for (int j = 0; j < 8; j++)
                    acc[i][j] += a[i] * bb[j];
        }
        __syncthreads();
    }
    #pragma unroll
    for (int i = 0; i < 8; i++) {
        int r = m0 + ty * 8 + i;
        #pragma unroll
        for (int j = 0; j < 8; j++) {
            int c = n0 + tx * 8 + j;
            float v = acc[i][j] + bias[c];
            if (MODE >= 1) v = fmaxf(v, 0.0f);
            if (MODE == 1) v *= scale;
            C[(size_t)r * N + c] = v;
        }
    }
}

// ---------------- attention: flash-style masked linear attention ------------
// grid: (L/64, B*H). Block: 256 threads, 64 q-rows, loop 64-wide s-tiles.
// W[l,s] = dot(maskQ(q[l]), maskK(k[s])) + [s global] dot(q[l], k[s])
// out[l] = (sum_s W[l,s] v[s]) / max(sum_s W[l,s], 1e-12)
__global__ void __launch_bounds__(256) attn_kernel(
    const float* __restrict__ qlin, const float* __restrict__ klin,
    const float* __restrict__ vlin, float* __restrict__ attn)
{
    extern __shared__ float sm[];
    float* Qs = sm;                 // 64 x 129 (masked q tile, padded)
    float* Ks = Qs + 64 * 129;      // 64 x 129 (masked k tile)
    float* Ss = Ks + 64 * 129;      // 64 x 65  (score tile)
    float* Vs = Ss + 64 * 65;       // 64 x 65  (v tile)
    float* dn = Vs + 64 * 65;       // 64       (denominator accum)

    int tid = threadIdx.x;
    int tx = tid & 15, ty = tid >> 4;
    int bh = blockIdx.y;
    int b = bh >> 4, h = bh & 15;
    int l0 = blockIdx.x * 64;

    // load Q tile (masked)
    for (int idx = tid; idx < 64 * 128; idx += 256) {
        int li = idx >> 7, d = idx & 127;
        int l = l0 + li;
        float qv = qlin[(size_t)(l * BATCH + b) * QKD + h * DQKh + d];
        int ws = g_ws[h * L_SEQ + l];
        bool keep = (h == 0) || ((unsigned)(d - ws) < 32u);
        Qs[li * 129 + d] = keep ? qv : 0.0f;
    }
    if (tid < 64) dn[tid] = 0.0f;

    float o[4][4] = {};

    for (int st = 0; st < 32; st++) {
        int s0 = st * 64;
        __syncthreads();  // protects Qs load (1st iter) + Ss/Vs/Ks reuse

        // load K tile (masked) + V tile
        for (int idx = tid; idx < 64 * 128; idx += 256) {
            int si = idx >> 7, d = idx & 127;
            int s = s0 + si;
            float kv = klin[(size_t)(s * BATCH + b) * QKD + h * DQKh + d];
            int ws = g_ws[h * L_SEQ + s];
            bool keep = (h == 0) || ((unsigned)(d - ws) < 32u);
            Ks[si * 129 + d] = keep ? kv : 0.0f;
        }
        for (int idx = tid; idx < 64 * 64; idx += 256) {
            int si = idx >> 6, d = idx & 63;
            Vs[si * 65 + d] = vlin[(size_t)((s0 + si) * BATCH + b) * EMB + h * DVh + d];
        }
        __syncthreads();

        // S = Qs @ Ks^T  (4x4 per thread)
        float sacc[4][4] = {};
        #pragma unroll 4
        for (int d = 0; d < 128; d++) {
            float a[4], bb[4];
            #pragma unroll
            for (int i = 0; i < 4; i++) a[i]  = Qs[(ty * 4 + i) * 129 + d];
            #pragma unroll
            for (int j = 0; j < 4; j++) bb[j] = Ks[(tx * 4 + j) * 129 + d];
            #pragma unroll
            for (int i = 0; i < 4; i++)
                #pragma unroll
                for (int j = 0; j < 4; j++)
                    sacc[i][j] += a[i] * bb[j];
        }

        // global-key correction: s in [0,16) or [2032,2048) add full q.k dot
        if (st == 0 || st == 31) {
            int g0 = (st == 0) ? 0 : 48;
            __syncthreads();
            for (int idx = tid; idx < 16 * 128; idx += 256) {   // reload 16 rows, unmasked
                int si = idx >> 7, d = idx & 127;
                int s = s0 + g0 + si;
                Ks[(g0 + si) * 129 + d] =
                    klin[(size_t)(s * BATCH + b) * QKD + h * DQKh + d];
            }
            __syncthreads();
            #pragma unroll
            for (int j = 0; j < 4; j++) {
                int sl = tx * 4 + j;
                if ((unsigned)(sl - g0) < 16u) {
                    #pragma unroll
                    for (int i = 0; i < 4; i++) {
                        int l = l0 + ty * 4 + i;
                        const float* qrow =
                            qlin + (size_t)(l * BATCH + b) * QKD + h * DQKh;
                        float acc = 0.0f;
                        for (int d = 0; d < 128; d++)
                            acc += qrow[d] * Ks[sl * 129 + d];
                        sacc[i][j] += acc;
                    }
                }
            }
        }

        // stage S in shared
        #pragma unroll
        for (int i = 0; i < 4; i++)
            #pragma unroll
            for (int j = 0; j < 4; j++)
                Ss[(ty * 4 + i) * 65 + tx * 4 + j] = sacc[i][j];
        __syncthreads();

        // denominator row-sums (conflict-free via pad-65)
        if (tid < 64) {
            float s = 0.0f;
            #pragma unroll 8
            for (int j = 0; j < 64; j++) s += Ss[tid * 65 + j];
            dn[tid] += s;
        }

        // Out += S @ V
        #pragma unroll 4
        for (int sk = 0; sk < 64; sk++) {
            float a[4], bb[4];
            #pragma unroll
            for (int i = 0; i < 4; i++) a[i]  = Ss[(ty * 4 + i) * 65 + sk];
            #pragma unroll
            for (int j = 0; j < 4; j++) bb[j] = Vs[sk * 65 + tx * 4 + j];
            #pragma unroll
            for (int i = 0; i < 4; i++)
                #pragma unroll
                for (int j = 0; j < 4; j++)
                    o[i][j] += a[i] * bb[j];
        }
    }
    __syncthreads();

    #pragma unroll
    for (int i = 0; i < 4; i++) {
        int l = l0 + ty * 4 + i;
        float inv = 1.0f / fmaxf(dn[ty * 4 + i], 1e-12f);
        #pragma unroll
        for (int j = 0; j < 4; j++) {
            attn[(size_t)(l * BATCH + b) * EMB + h * DVh + tx * 4 + j] =
                o[i][j] * inv;
        }
    }
}

// ---------------- launch -----------------------------------------------------
extern "C" void kernel_launch(void* const* d_in, const int* in_sizes, int n_in,
                              void* d_out, int out_size)
{
    (void)in_sizes; (void)n_in; (void)out_size;
    const float* query = (const float*)d_in[0];
    const float* key_  = (const float*)d_in[1];
    const float* value = (const float*)d_in[2];
    const float* Wq    = (const float*)d_in[3];
    const float* bq    = (const float*)d_in[4];
    const float* Wk    = (const float*)d_in[5];
    const float* bk    = (const float*)d_in[6];
    const float* Wv    = (const float*)d_in[7];
    const float* bv    = (const float*)d_in[8];
    const float* Wo    = (const float*)d_in[9];
    const float* bo    = (const float*)d_in[10];
    float* out = (float*)d_out;

    float *qlin, *klin, *vlin, *attn;
    cudaGetSymbolAddress((void**)&qlin, g_qlin);
    cudaGetSymbolAddress((void**)&klin, g_klin);
    cudaGetSymbolAddress((void**)&vlin, g_vlin);
    cudaGetSymbolAddress((void**)&attn, g_attn);

    const size_t ATTN_SMEM = (2 * 64 * 129 + 2 * 64 * 65 + 64) * sizeof(float);
    cudaFuncSetAttribute(attn_kernel,
                         cudaFuncAttributeMaxDynamicSharedMemorySize,
                         (int)ATTN_SMEM);

    build_ws_kernel<<<(NH * L_SEQ + 255) / 256, 256>>>();

    float scale = 1.0f / sqrtf((float)QKD);
    // q = relu(query @ Wq^T + bq) * scale   : M=4096 N=2048 K=1024
    sgemm_bias<1><<<dim3(QKD / 128, NROWS / 128), 256>>>(
        query, Wq, bq, qlin, NROWS, QKD, EMB, scale);
    // k = relu(key @ Wk^T + bk)
    sgemm_bias<2><<<dim3(QKD / 128, NROWS / 128), 256>>>(
        key_, Wk, bk, klin, NROWS, QKD, EMB, 1.0f);
    // v = value @ Wv^T + bv                 : N=1024
    sgemm_bias<0><<<dim3(EMB / 128, NROWS / 128), 256>>>(
        value, Wv, bv, vlin, NROWS, EMB, EMB, 1.0f);

    // attention
    attn_kernel<<<dim3(L_SEQ / 64, BATCH * NH), 256, ATTN_SMEM>>>(
        qlin, klin, vlin, attn);

    // out = attn @ Wo^T + bo
    sgemm_bias<0><<<dim3(EMB / 128, NROWS / 128), 256>>>(
        attn, Wo, bo, out, NROWS, EMB, EMB, 1.0f);
}